// round 11
// baseline (speedup 1.0000x reference)
#include <cuda_runtime.h>
#include <cstdint>
#include <math.h>

#define BB 8
#define LLEN 1024
#define DMODEL 1024
#define NH 16
#define DHEAD 64

// ---------------- static scratch (no allocations allowed) ----------------
// Q/K stored d-permuted (k-pair interleave); V, P, proj unpermuted.
// ctx stored d-permuted (feeds proj only).  All MMA operands tf32-rounded.
static __device__ float g_Q[(size_t)BB * NH * LLEN * DHEAD];
static __device__ float g_K[(size_t)BB * NH * LLEN * DHEAD];
static __device__ float g_V[(size_t)BB * NH * LLEN * DHEAD];
static __device__ float g_ctx[(size_t)BB * LLEN * DMODEL];
static __device__ float g_proj[(size_t)BB * LLEN * DMODEL];
static __device__ float g_attn[(size_t)BB * NH * LLEN * LLEN];   // fallback only
static __device__ float g_Xp[(size_t)BB * LLEN * DMODEL];        // packed X
static __device__ float g_Wp[(size_t)3 * DMODEL * DMODEL];       // packed W_{q,k,v}: [w][n][k]
static __device__ float g_Wop[(size_t)DMODEL * DMODEL];          // packed Wo: [n][k]

// ---------------- tf32 helpers ----------------
__device__ __forceinline__ unsigned f2tf32(float x) {
    unsigned r;
    asm("cvt.rna.tf32.f32 %0, %1;" : "=r"(r) : "f"(x));
    return r;
}
__device__ __forceinline__ float tf32f(float x) {
    return __uint_as_float(f2tf32(x));
}

__device__ __forceinline__ void mma_tf32(float* d, const unsigned* a, const unsigned* b) {
    asm volatile(
        "mma.sync.aligned.m16n8k8.row.col.f32.tf32.tf32.f32 "
        "{%0,%1,%2,%3}, {%4,%5,%6,%7}, {%8,%9}, {%0,%1,%2,%3};\n"
        : "+f"(d[0]), "+f"(d[1]), "+f"(d[2]), "+f"(d[3])
        : "r"(a[0]), "r"(a[1]), "r"(a[2]), "r"(a[3]), "r"(b[0]), "r"(b[1]));
}

__device__ __forceinline__ void cp16(void* smem_dst, const void* gsrc) {
    unsigned s = (unsigned)__cvta_generic_to_shared(smem_dst);
    asm volatile("cp.async.ca.shared.global [%0], [%1], 16;\n" :: "r"(s), "l"(gsrc));
}
__device__ __forceinline__ void cp_commit() {
    asm volatile("cp.async.commit_group;\n");
}
template <int N>
__device__ __forceinline__ void cp_wait() {
    asm volatile("cp.async.wait_group %0;\n" :: "n"(N));
}

// fragment-pair permutation: packed position p holds original k:
//   k(p) = (p&1) ? (p>>1)+4 : (p>>1)   (within each 8-group)
// so thread t's pair (k=t, k=t+4) sits at positions (2t, 2t+1) -> one LDS.64.
// epilogue scatter positions for a value at original within-group k:
//   pos(k) = (k<4) ? 2k : 2(k-4)+1

// =========================================================================
// Kernel 0a: pack X -> g_Xp (k-interleave within 8, tf32-rounded).
// =========================================================================
__global__ void prep_pack_x(const float* __restrict__ X)
{
    const size_t NG = (size_t)BB * LLEN * DMODEL / 8;   // 1M groups of 8
    for (size_t i = (size_t)blockIdx.x * blockDim.x + threadIdx.x;
         i < NG; i += (size_t)gridDim.x * blockDim.x) {
        const float* src = X + i * 8;
        float4 lo = *(const float4*)src;
        float4 hi = *(const float4*)(src + 4);
        float4 o0, o1;
        o0.x = tf32f(lo.x); o0.y = tf32f(hi.x); o0.z = tf32f(lo.y); o0.w = tf32f(hi.y);
        o1.x = tf32f(lo.z); o1.y = tf32f(hi.z); o1.z = tf32f(lo.w); o1.w = tf32f(hi.w);
        *(float4*)(g_Xp + i * 8) = o0;
        *(float4*)(g_Xp + i * 8 + 4) = o1;
    }
}

// =========================================================================
// Kernel 0b: transpose + pack weights.  z=0..2: Wq/Wk/Wv -> g_Wp[z];
// z=3: Wo -> g_Wop.   in: [k][n] row-major; out: [n][k] with k-interleave.
// =========================================================================
__global__ void prep_pack_w(const float* __restrict__ Wq,
                            const float* __restrict__ Wk,
                            const float* __restrict__ Wv,
                            const float* __restrict__ Wo)
{
    __shared__ float s[32][33];
    const int z = blockIdx.z;
    const float* __restrict__ src = (z == 0) ? Wq : (z == 1) ? Wk : (z == 2) ? Wv : Wo;
    float* __restrict__ dst = (z < 3) ? (g_Wp + (size_t)z * DMODEL * DMODEL) : g_Wop;

    const int k0 = blockIdx.y * 32;
    const int n0 = blockIdx.x * 32;
    const int tx = threadIdx.x, ty = threadIdx.y;

#pragma unroll
    for (int r = 0; r < 4; r++)
        s[ty + 8 * r][tx] = src[(size_t)(k0 + ty + 8 * r) * DMODEL + n0 + tx];
    __syncthreads();

#pragma unroll
    for (int r = 0; r < 4; r++) {
        const int n = n0 + ty + 8 * r;
        const int p7 = tx & 7;
        const int ksrc = (tx & ~7) + ((p7 & 1) ? (p7 >> 1) + 4 : (p7 >> 1));
        dst[(size_t)n * DMODEL + k0 + tx] = tf32f(s[ksrc][ty + 8 * r]);
    }
}

// =========================================================================
// Kernel 1: fused QKV projection (packed operands, LDS.64 fragments,
// CVT-free loop).  cp.async 2-stage, BM=BN=128, BK=16, 8 warps 4x2.
// Epilogue: Q/K written d-permuted + tf32; V written plain + tf32.
// =========================================================================
__global__ __launch_bounds__(256) void qkv_mma_kernel()
{
    __shared__ float As[2][128][20];
    __shared__ float Bs[2][128][20];

    const int tid  = threadIdx.x;
    const int warp = tid >> 5, lane = tid & 31;
    const int wm = warp >> 1, wn = warp & 1;
    const int g = lane >> 2, t = lane & 3;

    const int m0 = blockIdx.y * 128;
    const int ng = blockIdx.x * 128;
    const int wsel = ng >> 10;
    const int nl = ng & 1023;
    const float* __restrict__ Wb = g_Wp + (size_t)wsel * DMODEL * DMODEL;

    // staging: 512 16B chunks per operand, 2 per thread: row = c>>2, col4 = (c&3)*4
    const int r0c = (tid * 2) >> 2,     c0c = ((tid * 2) & 3) * 4;
    const int r1c = (tid * 2 + 1) >> 2, c1c = ((tid * 2 + 1) & 3) * 4;

    float acc[2][8][4];
#pragma unroll
    for (int i = 0; i < 2; i++)
#pragma unroll
        for (int j = 0; j < 8; j++)
#pragma unroll
            for (int c = 0; c < 4; c++) acc[i][j][c] = 0.f;

    cp16(&As[0][r0c][c0c], &g_Xp[(size_t)(m0 + r0c) * DMODEL + c0c]);
    cp16(&As[0][r1c][c1c], &g_Xp[(size_t)(m0 + r1c) * DMODEL + c1c]);
    cp16(&Bs[0][r0c][c0c], &Wb[(size_t)(nl + r0c) * DMODEL + c0c]);
    cp16(&Bs[0][r1c][c1c], &Wb[(size_t)(nl + r1c) * DMODEL + c1c]);
    cp_commit();

    const int NIT = DMODEL / 16;
    for (int it = 0; it < NIT; it++) {
        const int buf = it & 1;
        if (it + 1 < NIT) {
            const int k0 = (it + 1) * 16;
            cp16(&As[buf ^ 1][r0c][c0c], &g_Xp[(size_t)(m0 + r0c) * DMODEL + k0 + c0c]);
            cp16(&As[buf ^ 1][r1c][c1c], &g_Xp[(size_t)(m0 + r1c) * DMODEL + k0 + c1c]);
            cp16(&Bs[buf ^ 1][r0c][c0c], &Wb[(size_t)(nl + r0c) * DMODEL + k0 + c0c]);
            cp16(&Bs[buf ^ 1][r1c][c1c], &Wb[(size_t)(nl + r1c) * DMODEL + k0 + c1c]);
            cp_commit();
            cp_wait<1>();
        } else {
            cp_wait<0>();
        }
        __syncthreads();

#pragma unroll
        for (int ks = 0; ks < 16; ks += 8) {
            unsigned af[2][4], bf[8][2];
#pragma unroll
            for (int i = 0; i < 2; i++) {
                const int mr = wm * 32 + i * 16;
                float2 a0 = *(const float2*)&As[buf][mr + g][ks + 2 * t];
                float2 a1 = *(const float2*)&As[buf][mr + g + 8][ks + 2 * t];
                af[i][0] = __float_as_uint(a0.x);
                af[i][1] = __float_as_uint(a1.x);
                af[i][2] = __float_as_uint(a0.y);
                af[i][3] = __float_as_uint(a1.y);
            }
#pragma unroll
            for (int j = 0; j < 8; j++) {
                float2 b = *(const float2*)&Bs[buf][wn * 64 + j * 8 + g][ks + 2 * t];
                bf[j][0] = __float_as_uint(b.x);
                bf[j][1] = __float_as_uint(b.y);
            }
#pragma unroll
            for (int i = 0; i < 2; i++)
#pragma unroll
                for (int j = 0; j < 8; j++) mma_tf32(acc[i][j], af[i], bf[j]);
        }
        __syncthreads();
    }

    float* __restrict__ dst = (wsel == 0) ? g_Q : (wsel == 1 ? g_K : g_V);
    // scatter positions for within-8-group values k=2t (even) and k=2t+1 (odd)
    const int p_even = (t < 2) ? 4 * t : 4 * t - 7;
    const int p_odd  = (t < 2) ? 4 * t + 2 : 4 * t - 5;
#pragma unroll
    for (int i = 0; i < 2; i++) {
        const int r0 = m0 + wm * 32 + i * 16 + g;
        const int b = r0 >> 10, l = r0 & 1023;
#pragma unroll
        for (int j = 0; j < 8; j++) {
            const int cl = nl + wn * 64 + j * 8 + 2 * t;
            const int h = cl >> 6;
            const size_t base = ((size_t)(b * NH + h) * LLEN);
            if (wsel == 2) {
                // V: plain layout
                const int d = cl & 63;
                *(float2*)&dst[(base + l) * DHEAD + d] =
                    make_float2(tf32f(acc[i][j][0]), tf32f(acc[i][j][1]));
                *(float2*)&dst[(base + l + 8) * DHEAD + d] =
                    make_float2(tf32f(acc[i][j][2]), tf32f(acc[i][j][3]));
            } else {
                // Q/K: d-permuted layout
                const int dg = (cl & 63) & ~7;
                float* d0 = &dst[(base + l) * DHEAD + dg];
                float* d1 = &dst[(base + l + 8) * DHEAD + dg];
                d0[p_even] = tf32f(acc[i][j][0]);
                d0[p_odd]  = tf32f(acc[i][j][1]);
                d1[p_even] = tf32f(acc[i][j][2]);
                d1[p_odd]  = tf32f(acc[i][j][3]);
            }
        }
    }
}

// =========================================================================
// Kernel 2: FUSED scores + mask + softmax.  Q/K arrive d-permuted ->
// all fragment loads are LDS.64.  cp.async-pipelined K (16 x 64-row
// blocks), Q fragments hoisted, zero CVT.  Writes plain normalized P.
// =========================================================================
__global__ __launch_bounds__(256) void fused_attn_kernel(
    const int* __restrict__ mask,
    float* __restrict__ attn_ext)
{
    __shared__ float Qs[16][68];
    __shared__ float Ks[2][64][68];
    __shared__ float red[16][8];

    const int tid  = threadIdx.x;
    const int warp = tid >> 5, lane = tid & 31;
    const int g = lane >> 2, t = lane & 3;

    const int bh = blockIdx.y;
    const int b  = bh / NH;
    const int m0 = blockIdx.x * 16;
    const float* __restrict__ Q = g_Q + (size_t)bh * LLEN * DHEAD;
    const float* __restrict__ K = g_K + (size_t)bh * LLEN * DHEAD;

    {
        int m = tid >> 4, kq = (tid & 15) * 4;
        *(float4*)&Qs[m][kq] = *(const float4*)&Q[(size_t)(m0 + m) * DHEAD + kq];
    }

#pragma unroll
    for (int r = 0; r < 4; r++) {
        int c = tid + r * 256;
        int row = c >> 4, c4 = (c & 15) * 4;
        cp16(&Ks[0][row][c4], &K[(size_t)row * DHEAD + c4]);
    }
    cp_commit();
    __syncthreads();

    unsigned qf[8][4];
#pragma unroll
    for (int k8 = 0; k8 < 8; k8++) {
        float2 a0 = *(const float2*)&Qs[g][k8 * 8 + 2 * t];
        float2 a1 = *(const float2*)&Qs[g + 8][k8 * 8 + 2 * t];
        qf[k8][0] = __float_as_uint(a0.x);
        qf[k8][1] = __float_as_uint(a1.x);
        qf[k8][2] = __float_as_uint(a0.y);
        qf[k8][3] = __float_as_uint(a1.y);
    }

    float acc[16][4];
#pragma unroll
    for (int s = 0; s < 16; s++)
#pragma unroll
        for (int c = 0; c < 4; c++) acc[s][c] = 0.f;

#pragma unroll
    for (int it = 0; it < 16; it++) {
        const int buf = it & 1;
        if (it + 1 < 16) {
            const int n0 = (it + 1) * 64;
#pragma unroll
            for (int r = 0; r < 4; r++) {
                int c = tid + r * 256;
                int row = c >> 4, c4 = (c & 15) * 4;
                cp16(&Ks[buf ^ 1][row][c4], &K[(size_t)(n0 + row) * DHEAD + c4]);
            }
            cp_commit();
            cp_wait<1>();
        } else {
            cp_wait<0>();
        }
        __syncthreads();

        const int nr = warp * 8;
#pragma unroll
        for (int k8 = 0; k8 < 8; k8++) {
            float2 bv = *(const float2*)&Ks[buf][nr + g][k8 * 8 + 2 * t];
            unsigned bf[2];
            bf[0] = __float_as_uint(bv.x);
            bf[1] = __float_as_uint(bv.y);
            mma_tf32(acc[it], qf[k8], bf);
        }
        __syncthreads();
    }

    const float scale = 0.125f;
    const int ql = m0 + g, qh = m0 + g + 8;
    const int* __restrict__ mrl = mask + ((size_t)b * LLEN + ql) * LLEN;
    const int* __restrict__ mrh = mask + ((size_t)b * LLEN + qh) * LLEN;

    float mxl = -3e38f, mxh = -3e38f;
#pragma unroll
    for (int s = 0; s < 16; s++) {
        const int col = s * 64 + warp * 8 + 2 * t;
        const int2 mkl = *(const int2*)&mrl[col];
        const int2 mkh = *(const int2*)&mrh[col];
        float* a = acc[s];
        a[0] = mkl.x ? -1e9f : a[0] * scale;
        a[1] = mkl.y ? -1e9f : a[1] * scale;
        a[2] = mkh.x ? -1e9f : a[2] * scale;
        a[3] = mkh.y ? -1e9f : a[3] * scale;
        mxl = fmaxf(mxl, fmaxf(a[0], a[1]));
        mxh = fmaxf(mxh, fmaxf(a[2], a[3]));
    }
    mxl = fmaxf(mxl, __shfl_xor_sync(0xffffffffu, mxl, 1));
    mxl = fmaxf(mxl, __shfl_xor_sync(0xffffffffu, mxl, 2));
    mxh = fmaxf(mxh, __shfl_xor_sync(0xffffffffu, mxh, 1));
    mxh = fmaxf(mxh, __shfl_xor_sync(0xffffffffu, mxh, 2));
    if (t == 0) { red[g][warp] = mxl; red[g + 8][warp] = mxh; }
    __syncthreads();
    float Ml = red[g][0], Mh = red[g + 8][0];
#pragma unroll
    for (int w = 1; w < 8; w++) {
        Ml = fmaxf(Ml, red[g][w]);
        Mh = fmaxf(Mh, red[g + 8][w]);
    }
    __syncthreads();

    float sl = 0.f, sh = 0.f;
#pragma unroll
    for (int s = 0; s < 16; s++) {
        float* a = acc[s];
        a[0] = __expf(a[0] - Ml);
        a[1] = __expf(a[1] - Ml);
        a[2] = __expf(a[2] - Mh);
        a[3] = __expf(a[3] - Mh);
        sl += a[0] + a[1];
        sh += a[2] + a[3];
    }
    sl += __shfl_xor_sync(0xffffffffu, sl, 1);
    sl += __shfl_xor_sync(0xffffffffu, sl, 2);
    sh += __shfl_xor_sync(0xffffffffu, sh, 1);
    sh += __shfl_xor_sync(0xffffffffu, sh, 2);
    if (t == 0) { red[g][warp] = sl; red[g + 8][warp] = sh; }
    __syncthreads();
    float Sl = 0.f, Sh = 0.f;
#pragma unroll
    for (int w = 0; w < 8; w++) { Sl += red[g][w]; Sh += red[g + 8][w]; }
    const float invl = 1.0f / Sl, invh = 1.0f / Sh;

    float* __restrict__ P = attn_ext ? attn_ext : g_attn;
    float* __restrict__ prl = P + ((size_t)bh * LLEN + ql) * LLEN;
    float* __restrict__ prh = P + ((size_t)bh * LLEN + qh) * LLEN;
#pragma unroll
    for (int s = 0; s < 16; s++) {
        const int col = s * 64 + warp * 8 + 2 * t;
        const float* a = acc[s];
        *(float2*)&prl[col] = make_float2(a[0] * invl, a[1] * invl);
        *(float2*)&prh[col] = make_float2(a[2] * invh, a[3] * invh);
    }
}

// =========================================================================
// Kernel 3: context = P @ V (cp.async 2-stage).  P/V unpermuted (P is a
// required output; seq-axis fragments stay LDS.32).  Epilogue writes ctx
// d-PERMUTED + tf32-rounded for the proj GEMM.
// =========================================================================
__global__ __launch_bounds__(256) void pv_mma_kernel(const float* __restrict__ attn_ext)
{
    __shared__ float Ps[2][128][20];
    __shared__ float Vs[2][16][72];

    const int tid  = threadIdx.x;
    const int warp = tid >> 5, lane = tid & 31;
    const int wm = warp >> 1, wn = warp & 1;
    const int g = lane >> 2, t = lane & 3;

    const int bh = blockIdx.y;
    const int m0 = blockIdx.x * 128;
    const float* __restrict__ P =
        (attn_ext ? attn_ext : (const float*)g_attn) + (size_t)bh * LLEN * LLEN;
    const float* __restrict__ V = g_V + (size_t)bh * LLEN * DHEAD;

    const int prow = tid >> 2, pc4 = (tid & 3) * 4;
    const int vrow = tid >> 4, vc4 = (tid & 15) * 4;

    float acc[2][4][4];
#pragma unroll
    for (int i = 0; i < 2; i++)
#pragma unroll
        for (int j = 0; j < 4; j++)
#pragma unroll
            for (int c = 0; c < 4; c++) acc[i][j][c] = 0.f;

    {
        cp16(&Ps[0][prow][pc4],      &P[(size_t)(m0 + prow) * LLEN + pc4]);
        cp16(&Ps[0][prow + 64][pc4], &P[(size_t)(m0 + prow + 64) * LLEN + pc4]);
        cp16(&Vs[0][vrow][vc4],      &V[(size_t)vrow * DHEAD + vc4]);
        cp_commit();
    }

    const int NIT = LLEN / 16;
    for (int it = 0; it < NIT; it++) {
        const int buf = it & 1;
        if (it + 1 < NIT) {
            const int k0 = (it + 1) * 16;
            cp16(&Ps[buf ^ 1][prow][pc4],      &P[(size_t)(m0 + prow) * LLEN + k0 + pc4]);
            cp16(&Ps[buf ^ 1][prow + 64][pc4], &P[(size_t)(m0 + prow + 64) * LLEN + k0 + pc4]);
            cp16(&Vs[buf ^ 1][vrow][vc4],      &V[(size_t)(k0 + vrow) * DHEAD + vc4]);
            cp_commit();
            cp_wait<1>();
        } else {
            cp_wait<0>();
        }
        __syncthreads();

#pragma unroll
        for (int ks = 0; ks < 16; ks += 8) {
            unsigned af[2][4], bf[4][2];
#pragma unroll
            for (int i = 0; i < 2; i++) {
                int mr = wm * 32 + i * 16;
                af[i][0] = f2tf32(Ps[buf][mr + g][ks + t]);
                af[i][1] = f2tf32(Ps[buf][mr + g + 8][ks + t]);
                af[i][2] = f2tf32(Ps[buf][mr + g][ks + t + 4]);
                af[i][3] = f2tf32(Ps[buf][mr + g + 8][ks + t + 4]);
            }
#pragma unroll
            for (int j = 0; j < 4; j++) {
                int nr = wn * 32 + j * 8;
                bf[j][0] = __float_as_uint(Vs[buf][ks + t][nr + g]);
                bf[j][1] = __float_as_uint(Vs[buf][ks + t + 4][nr + g]);
            }
#pragma unroll
            for (int i = 0; i < 2; i++)
#pragma unroll
                for (int j = 0; j < 4; j++) mma_tf32(acc[i][j], af[i], bf[j]);
        }
        __syncthreads();
    }

    const int b = bh / NH, h = bh % NH;
    const int p_even = (t < 2) ? 4 * t : 4 * t - 7;
    const int p_odd  = (t < 2) ? 4 * t + 2 : 4 * t - 5;
#pragma unroll
    for (int i = 0; i < 2; i++) {
        const int l0 = m0 + wm * 32 + i * 16 + g;
#pragma unroll
        for (int j = 0; j < 4; j++) {
            const int dg = h * 64 + wn * 32 + j * 8;    // 8-group base in dmodel
            float* d0 = &g_ctx[((size_t)(b * LLEN + l0)) * DMODEL + dg];
            float* d1 = &g_ctx[((size_t)(b * LLEN + l0 + 8)) * DMODEL + dg];
            d0[p_even] = tf32f(acc[i][j][0]);
            d0[p_odd]  = tf32f(acc[i][j][1]);
            d1[p_even] = tf32f(acc[i][j][2]);
            d1[p_odd]  = tf32f(acc[i][j][3]);
        }
    }
}

// =========================================================================
// Kernel 4: output projection (ctx + Wop both packed: LDS.64 fragments,
// CVT-free).  Same structure as qkv.  Writes plain g_proj.
// =========================================================================
__global__ __launch_bounds__(256) void proj_mma_kernel()
{
    __shared__ float As[2][128][20];
    __shared__ float Bs[2][128][20];

    const int tid  = threadIdx.x;
    const int warp = tid >> 5, lane = tid & 31;
    const int wm = warp >> 1, wn = warp & 1;
    const int g = lane >> 2, t = lane & 3;

    const int m0 = blockIdx.y * 128;
    const int n0 = blockIdx.x * 128;

    const int r0c = (tid * 2) >> 2,     c0c = ((tid * 2) & 3) * 4;
    const int r1c = (tid * 2 + 1) >> 2, c1c = ((tid * 2 + 1) & 3) * 4;

    float acc[2][8][4];
#pragma unroll
    for (int i = 0; i < 2; i++)
#pragma unroll
        for (int j = 0; j < 8; j++)
#pragma unroll
            for (int c = 0; c < 4; c++) acc[i][j][c] = 0.f;

    cp16(&As[0][r0c][c0c], &g_ctx[(size_t)(m0 + r0c) * DMODEL + c0c]);
    cp16(&As[0][r1c][c1c], &g_ctx[(size_t)(m0 + r1c) * DMODEL + c1c]);
    cp16(&Bs[0][r0c][c0c], &g_Wop[(size_t)(n0 + r0c) * DMODEL + c0c]);
    cp16(&Bs[0][r1c][c1c], &g_Wop[(size_t)(n0 + r1c) * DMODEL + c1c]);
    cp_commit();

    const int NIT = DMODEL / 16;
    for (int it = 0; it < NIT; it++) {
        const int buf = it & 1;
        if (it + 1 < NIT) {
            const int k0 = (it + 1) * 16;
            cp16(&As[buf ^ 1][r0c][c0c], &g_ctx[(size_t)(m0 + r0c) * DMODEL + k0 + c0c]);
            cp16(&As[buf ^ 1][r1c][c1c], &g_ctx[(size_t)(m0 + r1c) * DMODEL + k0 + c1c]);
            cp16(&Bs[buf ^ 1][r0c][c0c], &g_Wop[(size_t)(n0 + r0c) * DMODEL + k0 + c0c]);
            cp16(&Bs[buf ^ 1][r1c][c1c], &g_Wop[(size_t)(n0 + r1c) * DMODEL + k0 + c1c]);
            cp_commit();
            cp_wait<1>();
        } else {
            cp_wait<0>();
        }
        __syncthreads();

#pragma unroll
        for (int ks = 0; ks < 16; ks += 8) {
            unsigned af[2][4], bf[8][2];
#pragma unroll
            for (int i = 0; i < 2; i++) {
                const int mr = wm * 32 + i * 16;
                float2 a0 = *(const float2*)&As[buf][mr + g][ks + 2 * t];
                float2 a1 = *(const float2*)&As[buf][mr + g + 8][ks + 2 * t];
                af[i][0] = __float_as_uint(a0.x);
                af[i][1] = __float_as_uint(a1.x);
                af[i][2] = __float_as_uint(a0.y);
                af[i][3] = __float_as_uint(a1.y);
            }
#pragma unroll
            for (int j = 0; j < 8; j++) {
                float2 b = *(const float2*)&Bs[buf][wn * 64 + j * 8 + g][ks + 2 * t];
                bf[j][0] = __float_as_uint(b.x);
                bf[j][1] = __float_as_uint(b.y);
            }
#pragma unroll
            for (int i = 0; i < 2; i++)
#pragma unroll
                for (int j = 0; j < 8; j++) mma_tf32(acc[i][j], af[i], bf[j]);
        }
        __syncthreads();
    }

#pragma unroll
    for (int i = 0; i < 2; i++) {
        int r0 = m0 + wm * 32 + i * 16 + g;
#pragma unroll
        for (int j = 0; j < 8; j++) {
            int c = n0 + wn * 64 + j * 8 + 2 * t;
            float2 v0 = make_float2(acc[i][j][0], acc[i][j][1]);
            float2 v1 = make_float2(acc[i][j][2], acc[i][j][3]);
            *(float2*)&g_proj[(size_t)r0 * DMODEL + c] = v0;
            *(float2*)&g_proj[(size_t)(r0 + 8) * DMODEL + c] = v1;
        }
    }
}

// =========================================================================
// Kernel 5: residual + LayerNorm (unchanged).
// =========================================================================
__global__ void ln_kernel(const float* __restrict__ X,
                          const float* __restrict__ gamma,
                          const float* __restrict__ beta,
                          float* __restrict__ out)
{
    const int row = blockIdx.x;
    const int tid = threadIdx.x;
    const float* __restrict__ pr = g_proj + (size_t)row * DMODEL;
    const float* __restrict__ xr = X + (size_t)row * DMODEL;

    float4 p = reinterpret_cast<const float4*>(pr)[tid];
    float4 x = reinterpret_cast<const float4*>(xr)[tid];
    float y0 = p.x + x.x, y1 = p.y + x.y, y2 = p.z + x.z, y3 = p.w + x.w;

    __shared__ float red[8];
    float s = y0 + y1 + y2 + y3;
#pragma unroll
    for (int o = 16; o > 0; o >>= 1) s += __shfl_xor_sync(0xffffffffu, s, o);
    if ((tid & 31) == 0) red[tid >> 5] = s;
    __syncthreads();
    float tot = red[0];
#pragma unroll
    for (int w = 1; w < 8; w++) tot += red[w];
    const float mu = tot * (1.0f / DMODEL);
    __syncthreads();

    float d0 = y0 - mu, d1 = y1 - mu, d2 = y2 - mu, d3 = y3 - mu;
    float sq = d0 * d0 + d1 * d1 + d2 * d2 + d3 * d3;
#pragma unroll
    for (int o = 16; o > 0; o >>= 1) sq += __shfl_xor_sync(0xffffffffu, sq, o);
    if ((tid & 31) == 0) red[tid >> 5] = sq;
    __syncthreads();
    float tot2 = red[0];
#pragma unroll
    for (int w = 1; w < 8; w++) tot2 += red[w];
    const float var = tot2 * (1.0f / DMODEL);
    const float inv = rsqrtf(var + 1e-6f);

    const int c = tid * 4;
    float* __restrict__ orow = out + (size_t)row * DMODEL;
    orow[c + 0] = d0 * inv * gamma[c + 0] + beta[c + 0];
    orow[c + 1] = d1 * inv * gamma[c + 1] + beta[c + 1];
    orow[c + 2] = d2 * inv * gamma[c + 2] + beta[c + 2];
    orow[c + 3] = d3 * inv * gamma[c + 3] + beta[c + 3];
}

// =========================================================================
extern "C" void kernel_launch(void* const* d_in, const int* in_sizes, int n_in,
                              void* d_out, int out_size)
{
    const float* X     = (const float*)d_in[0];
    const int*   mask  = (const int*)d_in[1];
    const float* Wq    = (const float*)d_in[2];
    const float* Wk    = (const float*)d_in[3];
    const float* Wv    = (const float*)d_in[4];
    const float* Wo    = (const float*)d_in[5];
    const float* gamma = (const float*)d_in[6];
    const float* beta  = (const float*)d_in[7];
    float* out = (float*)d_out;

    const long long LN_N   = (long long)BB * LLEN * DMODEL;
    const long long ATTN_N = (long long)BB * NH * LLEN * LLEN;
    float* attn_ptr = ((long long)out_size >= LN_N + ATTN_N) ? (out + LN_N) : nullptr;

    prep_pack_x<<<2048, 256>>>(X);
    prep_pack_w<<<dim3(32, 32, 4), dim3(32, 8)>>>(Wq, Wk, Wv, Wo);
    qkv_mma_kernel<<<dim3(24, 64), 256>>>();
    fused_attn_kernel<<<dim3(64, BB * NH), 256>>>(mask, attn_ptr);
    pv_mma_kernel<<<dim3(8, BB * NH), 256>>>(attn_ptr);
    proj_mma_kernel<<<dim3(8, 64), 256>>>();
    ln_kernel<<<BB * LLEN, 256>>>(X, gamma, beta, out);
}

// round 12
// speedup vs baseline: 1.3557x; 1.3557x over previous
#include <cuda_runtime.h>
#include <cstdint>
#include <math.h>

#define BB 8
#define LLEN 1024
#define DMODEL 1024
#define NH 16
#define DHEAD 64

// ---------------- static scratch (no allocations allowed) ----------------
// g_Q/g_K/g_V/g_ctx hold tf32-rounded bit patterns (stored as float bits).
static __device__ float g_Q[(size_t)BB * NH * LLEN * DHEAD];
static __device__ float g_K[(size_t)BB * NH * LLEN * DHEAD];
static __device__ float g_V[(size_t)BB * NH * LLEN * DHEAD];
static __device__ float g_ctx[(size_t)BB * LLEN * DMODEL];
static __device__ float g_proj[(size_t)BB * LLEN * DMODEL];
static __device__ float g_attn[(size_t)BB * NH * LLEN * LLEN];   // fallback only
static __device__ float g_Woc[(size_t)DMODEL * DMODEL];          // tf32-rounded Wo

// ---------------- tf32 warp-MMA helpers ----------------
__device__ __forceinline__ unsigned f2tf32(float x) {
    unsigned r;
    asm("cvt.rna.tf32.f32 %0, %1;" : "=r"(r) : "f"(x));
    return r;
}
__device__ __forceinline__ float tf32f(float x) {
    return __uint_as_float(f2tf32(x));
}

__device__ __forceinline__ void mma_tf32(float* d, const unsigned* a, const unsigned* b) {
    asm volatile(
        "mma.sync.aligned.m16n8k8.row.col.f32.tf32.tf32.f32 "
        "{%0,%1,%2,%3}, {%4,%5,%6,%7}, {%8,%9}, {%0,%1,%2,%3};\n"
        : "+f"(d[0]), "+f"(d[1]), "+f"(d[2]), "+f"(d[3])
        : "r"(a[0]), "r"(a[1]), "r"(a[2]), "r"(a[3]), "r"(b[0]), "r"(b[1]));
}

__device__ __forceinline__ void cp16(void* smem_dst, const void* gsrc) {
    unsigned s = (unsigned)__cvta_generic_to_shared(smem_dst);
    asm volatile("cp.async.ca.shared.global [%0], [%1], 16;\n" :: "r"(s), "l"(gsrc));
}
__device__ __forceinline__ void cp_commit() {
    asm volatile("cp.async.commit_group;\n");
}
template <int N>
__device__ __forceinline__ void cp_wait() {
    asm volatile("cp.async.wait_group %0;\n" :: "n"(N));
}

// =========================================================================
// Kernel 0: convert only Wo (4MB) to tf32 bits — proj becomes CVT-free.
// =========================================================================
__global__ void prep_wo_kernel(const float* __restrict__ Wo)
{
    const size_t N4 = (size_t)DMODEL * DMODEL / 4;
    for (size_t i = (size_t)blockIdx.x * blockDim.x + threadIdx.x;
         i < N4; i += (size_t)gridDim.x * blockDim.x) {
        float4 v = ((const float4*)Wo)[i];
        v.x = tf32f(v.x); v.y = tf32f(v.y); v.z = tf32f(v.z); v.w = tf32f(v.w);
        ((float4*)g_Woc)[i] = v;
    }
}

// =========================================================================
// Kernel 1: fused QKV projection, cp.async 2-stage (R8 version).
// =========================================================================
__global__ __launch_bounds__(256) void qkv_mma_kernel(
    const float* __restrict__ X,
    const float* __restrict__ Wq,
    const float* __restrict__ Wk,
    const float* __restrict__ Wv)
{
    __shared__ float As[2][128][20];
    __shared__ float Bs[2][16][136];

    const int tid  = threadIdx.x;
    const int warp = tid >> 5, lane = tid & 31;
    const int wm = warp >> 1, wn = warp & 1;
    const int g = lane >> 2, t = lane & 3;

    const int m0 = blockIdx.y * 128;
    const int ng = blockIdx.x * 128;
    const int wsel = ng >> 10;
    const int nl = ng & 1023;
    const float* __restrict__ W = (wsel == 0) ? Wq : (wsel == 1 ? Wk : Wv);

    const int am0 = (tid * 2) >> 2,      ach0 = ((tid * 2) & 3) * 4;
    const int am1 = (tid * 2 + 1) >> 2,  ach1 = ((tid * 2 + 1) & 3) * 4;
    const int bk0 = (tid * 2) >> 5,      bch0 = ((tid * 2) & 31) * 4;
    const int bk1 = (tid * 2 + 1) >> 5,  bch1 = ((tid * 2 + 1) & 31) * 4;

    float acc[2][8][4];
#pragma unroll
    for (int i = 0; i < 2; i++)
#pragma unroll
        for (int j = 0; j < 8; j++)
#pragma unroll
            for (int c = 0; c < 4; c++) acc[i][j][c] = 0.f;

    cp16(&As[0][am0][ach0], &X[(size_t)(m0 + am0) * DMODEL + ach0]);
    cp16(&As[0][am1][ach1], &X[(size_t)(m0 + am1) * DMODEL + ach1]);
    cp16(&Bs[0][bk0][bch0], &W[(size_t)bk0 * DMODEL + nl + bch0]);
    cp16(&Bs[0][bk1][bch1], &W[(size_t)bk1 * DMODEL + nl + bch1]);
    cp_commit();

    const int NIT = DMODEL / 16;
    for (int it = 0; it < NIT; it++) {
        const int buf = it & 1;
        if (it + 1 < NIT) {
            const int k0 = (it + 1) * 16;
            cp16(&As[buf ^ 1][am0][ach0], &X[(size_t)(m0 + am0) * DMODEL + k0 + ach0]);
            cp16(&As[buf ^ 1][am1][ach1], &X[(size_t)(m0 + am1) * DMODEL + k0 + ach1]);
            cp16(&Bs[buf ^ 1][bk0][bch0], &W[(size_t)(k0 + bk0) * DMODEL + nl + bch0]);
            cp16(&Bs[buf ^ 1][bk1][bch1], &W[(size_t)(k0 + bk1) * DMODEL + nl + bch1]);
            cp_commit();
            cp_wait<1>();
        } else {
            cp_wait<0>();
        }
        __syncthreads();

#pragma unroll
        for (int ks = 0; ks < 16; ks += 8) {
            unsigned af[2][4], bf[8][2];
#pragma unroll
            for (int i = 0; i < 2; i++) {
                int mr = wm * 32 + i * 16;
                af[i][0] = f2tf32(As[buf][mr + g][ks + t]);
                af[i][1] = f2tf32(As[buf][mr + g + 8][ks + t]);
                af[i][2] = f2tf32(As[buf][mr + g][ks + t + 4]);
                af[i][3] = f2tf32(As[buf][mr + g + 8][ks + t + 4]);
            }
#pragma unroll
            for (int j = 0; j < 8; j++) {
                int nr = wn * 64 + j * 8;
                bf[j][0] = f2tf32(Bs[buf][ks + t][nr + g]);
                bf[j][1] = f2tf32(Bs[buf][ks + t + 4][nr + g]);
            }
#pragma unroll
            for (int i = 0; i < 2; i++)
#pragma unroll
                for (int j = 0; j < 8; j++) mma_tf32(acc[i][j], af[i], bf[j]);
        }
        __syncthreads();
    }

    float* __restrict__ dst = (wsel == 0) ? g_Q : (wsel == 1 ? g_K : g_V);
#pragma unroll
    for (int i = 0; i < 2; i++) {
        int r0 = m0 + wm * 32 + i * 16 + g;
        int b = r0 >> 10, l = r0 & 1023;
#pragma unroll
        for (int j = 0; j < 8; j++) {
            int cl = nl + wn * 64 + j * 8 + 2 * t;
            int h = cl >> 6, d = cl & 63;
            size_t base = ((size_t)(b * NH + h) * LLEN);
            float2 v0 = make_float2(tf32f(acc[i][j][0]), tf32f(acc[i][j][1]));
            float2 v1 = make_float2(tf32f(acc[i][j][2]), tf32f(acc[i][j][3]));
            *(float2*)&dst[(base + l) * DHEAD + d] = v0;
            *(float2*)&dst[(base + l + 8) * DHEAD + d] = v1;
        }
    }
}

// =========================================================================
// Kernel 2: FUSED scores + mask + softmax, cp.async-pipelined K.
// R8 version + __launch_bounds__(256, 2): cap regs at 128 so 2 CTAs/SM
// co-reside (was 130 regs -> 1 CTA/SM, occ 12.4%).
// =========================================================================
__global__ __launch_bounds__(256, 2) void fused_attn_kernel(
    const int* __restrict__ mask,
    float* __restrict__ attn_ext)
{
    __shared__ float Qs[16][68];        //  4352 B
    __shared__ float Ks[2][64][68];     // 34816 B
    __shared__ float red[16][8];        //   512 B

    const int tid  = threadIdx.x;
    const int warp = tid >> 5, lane = tid & 31;
    const int g = lane >> 2, t = lane & 3;

    const int bh = blockIdx.y;
    const int b  = bh / NH;
    const int m0 = blockIdx.x * 16;
    const float* __restrict__ Q = g_Q + (size_t)bh * LLEN * DHEAD;
    const float* __restrict__ K = g_K + (size_t)bh * LLEN * DHEAD;

    // stage Q strip 16x64 (raw copy; already tf32 bits)
    {
        int m = tid >> 4, kq = (tid & 15) * 4;
        *(float4*)&Qs[m][kq] = *(const float4*)&Q[(size_t)(m0 + m) * DHEAD + kq];
    }

    // prologue: K block 0
#pragma unroll
    for (int r = 0; r < 4; r++) {
        int c = tid + r * 256;
        int row = c >> 4, c4 = (c & 15) * 4;
        cp16(&Ks[0][row][c4], &K[(size_t)row * DHEAD + c4]);
    }
    cp_commit();
    __syncthreads();

    // hoist Q fragments: 8 k-steps x 4 regs
    unsigned qf[8][4];
#pragma unroll
    for (int k8 = 0; k8 < 8; k8++) {
        const int ks = k8 * 8;
        qf[k8][0] = __float_as_uint(Qs[g][ks + t]);
        qf[k8][1] = __float_as_uint(Qs[g + 8][ks + t]);
        qf[k8][2] = __float_as_uint(Qs[g][ks + t + 4]);
        qf[k8][3] = __float_as_uint(Qs[g + 8][ks + t + 4]);
    }

    float acc[16][4];
#pragma unroll
    for (int s = 0; s < 16; s++)
#pragma unroll
        for (int c = 0; c < 4; c++) acc[s][c] = 0.f;

    // ---------------- Phase A: S = Q K^T over 16 pipelined blocks --------
#pragma unroll
    for (int it = 0; it < 16; it++) {
        const int buf = it & 1;
        if (it + 1 < 16) {
            const int n0 = (it + 1) * 64;
#pragma unroll
            for (int r = 0; r < 4; r++) {
                int c = tid + r * 256;
                int row = c >> 4, c4 = (c & 15) * 4;
                cp16(&Ks[buf ^ 1][row][c4], &K[(size_t)(n0 + row) * DHEAD + c4]);
            }
            cp_commit();
            cp_wait<1>();
        } else {
            cp_wait<0>();
        }
        __syncthreads();

        const int nr = warp * 8;
#pragma unroll
        for (int k8 = 0; k8 < 8; k8++) {
            const int ks = k8 * 8;
            unsigned bf[2];
            bf[0] = __float_as_uint(Ks[buf][nr + g][ks + t]);
            bf[1] = __float_as_uint(Ks[buf][nr + g][ks + t + 4]);
            mma_tf32(acc[it], qf[k8], bf);
        }
        __syncthreads();
    }

    // ---- scale + mask + row max ----
    const float scale = 0.125f;
    const int ql = m0 + g, qh = m0 + g + 8;
    const int* __restrict__ mrl = mask + ((size_t)b * LLEN + ql) * LLEN;
    const int* __restrict__ mrh = mask + ((size_t)b * LLEN + qh) * LLEN;

    float mxl = -3e38f, mxh = -3e38f;
#pragma unroll
    for (int s = 0; s < 16; s++) {
        const int col = s * 64 + warp * 8 + 2 * t;
        const int2 mkl = *(const int2*)&mrl[col];
        const int2 mkh = *(const int2*)&mrh[col];
        float* a = acc[s];
        a[0] = mkl.x ? -1e9f : a[0] * scale;
        a[1] = mkl.y ? -1e9f : a[1] * scale;
        a[2] = mkh.x ? -1e9f : a[2] * scale;
        a[3] = mkh.y ? -1e9f : a[3] * scale;
        mxl = fmaxf(mxl, fmaxf(a[0], a[1]));
        mxh = fmaxf(mxh, fmaxf(a[2], a[3]));
    }
    mxl = fmaxf(mxl, __shfl_xor_sync(0xffffffffu, mxl, 1));
    mxl = fmaxf(mxl, __shfl_xor_sync(0xffffffffu, mxl, 2));
    mxh = fmaxf(mxh, __shfl_xor_sync(0xffffffffu, mxh, 1));
    mxh = fmaxf(mxh, __shfl_xor_sync(0xffffffffu, mxh, 2));
    if (t == 0) { red[g][warp] = mxl; red[g + 8][warp] = mxh; }
    __syncthreads();
    float Ml = red[g][0], Mh = red[g + 8][0];
#pragma unroll
    for (int w = 1; w < 8; w++) {
        Ml = fmaxf(Ml, red[g][w]);
        Mh = fmaxf(Mh, red[g + 8][w]);
    }
    __syncthreads();

    // ---- exp + row sum ----
    float sl = 0.f, sh = 0.f;
#pragma unroll
    for (int s = 0; s < 16; s++) {
        float* a = acc[s];
        a[0] = __expf(a[0] - Ml);
        a[1] = __expf(a[1] - Ml);
        a[2] = __expf(a[2] - Mh);
        a[3] = __expf(a[3] - Mh);
        sl += a[0] + a[1];
        sh += a[2] + a[3];
    }
    sl += __shfl_xor_sync(0xffffffffu, sl, 1);
    sl += __shfl_xor_sync(0xffffffffu, sl, 2);
    sh += __shfl_xor_sync(0xffffffffu, sh, 1);
    sh += __shfl_xor_sync(0xffffffffu, sh, 2);
    if (t == 0) { red[g][warp] = sl; red[g + 8][warp] = sh; }
    __syncthreads();
    float Sl = 0.f, Sh = 0.f;
#pragma unroll
    for (int w = 0; w < 8; w++) { Sl += red[g][w]; Sh += red[g + 8][w]; }
    const float invl = 1.0f / Sl, invh = 1.0f / Sh;

    // ---- normalized single-pass P write (exact f32) ----
    float* __restrict__ P = attn_ext ? attn_ext : g_attn;
    float* __restrict__ prl = P + ((size_t)bh * LLEN + ql) * LLEN;
    float* __restrict__ prh = P + ((size_t)bh * LLEN + qh) * LLEN;
#pragma unroll
    for (int s = 0; s < 16; s++) {
        const int col = s * 64 + warp * 8 + 2 * t;
        const float* a = acc[s];
        *(float2*)&prl[col] = make_float2(a[0] * invl, a[1] * invl);
        *(float2*)&prh[col] = make_float2(a[2] * invh, a[3] * invh);
    }
}

// =========================================================================
// Kernel 3: context = P @ V (R8 version, unchanged).
// =========================================================================
__global__ __launch_bounds__(256) void pv_mma_kernel(const float* __restrict__ attn_ext)
{
    __shared__ float Ps[2][128][20];
    __shared__ float Vs[2][16][72];

    const int tid  = threadIdx.x;
    const int warp = tid >> 5, lane = tid & 31;
    const int wm = warp >> 1, wn = warp & 1;
    const int g = lane >> 2, t = lane & 3;

    const int bh = blockIdx.y;
    const int m0 = blockIdx.x * 128;
    const float* __restrict__ P =
        (attn_ext ? attn_ext : (const float*)g_attn) + (size_t)bh * LLEN * LLEN;
    const float* __restrict__ V = g_V + (size_t)bh * LLEN * DHEAD;

    const int prow = tid >> 2, pc4 = (tid & 3) * 4;
    const int vrow = tid >> 4, vc4 = (tid & 15) * 4;

    float acc[2][4][4];
#pragma unroll
    for (int i = 0; i < 2; i++)
#pragma unroll
        for (int j = 0; j < 4; j++)
#pragma unroll
            for (int c = 0; c < 4; c++) acc[i][j][c] = 0.f;

    {
        cp16(&Ps[0][prow][pc4],      &P[(size_t)(m0 + prow) * LLEN + pc4]);
        cp16(&Ps[0][prow + 64][pc4], &P[(size_t)(m0 + prow + 64) * LLEN + pc4]);
        cp16(&Vs[0][vrow][vc4],      &V[(size_t)vrow * DHEAD + vc4]);
        cp_commit();
    }

    const int NIT = LLEN / 16;
    for (int it = 0; it < NIT; it++) {
        const int buf = it & 1;
        if (it + 1 < NIT) {
            const int k0 = (it + 1) * 16;
            cp16(&Ps[buf ^ 1][prow][pc4],      &P[(size_t)(m0 + prow) * LLEN + k0 + pc4]);
            cp16(&Ps[buf ^ 1][prow + 64][pc4], &P[(size_t)(m0 + prow + 64) * LLEN + k0 + pc4]);
            cp16(&Vs[buf ^ 1][vrow][vc4],      &V[(size_t)(k0 + vrow) * DHEAD + vc4]);
            cp_commit();
            cp_wait<1>();
        } else {
            cp_wait<0>();
        }
        __syncthreads();

#pragma unroll
        for (int ks = 0; ks < 16; ks += 8) {
            unsigned af[2][4], bf[4][2];
#pragma unroll
            for (int i = 0; i < 2; i++) {
                int mr = wm * 32 + i * 16;
                af[i][0] = f2tf32(Ps[buf][mr + g][ks + t]);
                af[i][1] = f2tf32(Ps[buf][mr + g + 8][ks + t]);
                af[i][2] = f2tf32(Ps[buf][mr + g][ks + t + 4]);
                af[i][3] = f2tf32(Ps[buf][mr + g + 8][ks + t + 4]);
            }
#pragma unroll
            for (int j = 0; j < 4; j++) {
                int nr = wn * 32 + j * 8;
                bf[j][0] = __float_as_uint(Vs[buf][ks + t][nr + g]);
                bf[j][1] = __float_as_uint(Vs[buf][ks + t + 4][nr + g]);
            }
#pragma unroll
            for (int i = 0; i < 2; i++)
#pragma unroll
                for (int j = 0; j < 4; j++) mma_tf32(acc[i][j], af[i], bf[j]);
        }
        __syncthreads();
    }

    const int b = bh / NH, h = bh % NH;
#pragma unroll
    for (int i = 0; i < 2; i++) {
        int l0 = m0 + wm * 32 + i * 16 + g;
#pragma unroll
        for (int j = 0; j < 4; j++) {
            int d = wn * 32 + j * 8 + 2 * t;
            float2 v0 = make_float2(tf32f(acc[i][j][0]), tf32f(acc[i][j][1]));
            float2 v1 = make_float2(tf32f(acc[i][j][2]), tf32f(acc[i][j][3]));
            *(float2*)&g_ctx[((size_t)(b * LLEN + l0)) * DMODEL + h * 64 + d] = v0;
            *(float2*)&g_ctx[((size_t)(b * LLEN + l0 + 8)) * DMODEL + h * 64 + d] = v1;
        }
    }
}

// =========================================================================
// Kernel 4: output projection (R8 version, unchanged).
// =========================================================================
__global__ __launch_bounds__(256) void proj_mma_kernel()
{
    __shared__ float As[2][128][20];
    __shared__ float Bs[2][16][136];

    const int tid  = threadIdx.x;
    const int warp = tid >> 5, lane = tid & 31;
    const int wm = warp >> 1, wn = warp & 1;
    const int g = lane >> 2, t = lane & 3;

    const int m0 = blockIdx.y * 128;
    const int n0 = blockIdx.x * 128;
    const float* __restrict__ Wo = g_Woc;

    const int am0 = (tid * 2) >> 2,      ach0 = ((tid * 2) & 3) * 4;
    const int am1 = (tid * 2 + 1) >> 2,  ach1 = ((tid * 2 + 1) & 3) * 4;
    const int bk0 = (tid * 2) >> 5,      bch0 = ((tid * 2) & 31) * 4;
    const int bk1 = (tid * 2 + 1) >> 5,  bch1 = ((tid * 2 + 1) & 31) * 4;

    float acc[2][8][4];
#pragma unroll
    for (int i = 0; i < 2; i++)
#pragma unroll
        for (int j = 0; j < 8; j++)
#pragma unroll
            for (int c = 0; c < 4; c++) acc[i][j][c] = 0.f;

    cp16(&As[0][am0][ach0], &g_ctx[(size_t)(m0 + am0) * DMODEL + ach0]);
    cp16(&As[0][am1][ach1], &g_ctx[(size_t)(m0 + am1) * DMODEL + ach1]);
    cp16(&Bs[0][bk0][bch0], &Wo[(size_t)bk0 * DMODEL + n0 + bch0]);
    cp16(&Bs[0][bk1][bch1], &Wo[(size_t)bk1 * DMODEL + n0 + bch1]);
    cp_commit();

    const int NIT = DMODEL / 16;
    for (int it = 0; it < NIT; it++) {
        const int buf = it & 1;
        if (it + 1 < NIT) {
            const int k0 = (it + 1) * 16;
            cp16(&As[buf ^ 1][am0][ach0], &g_ctx[(size_t)(m0 + am0) * DMODEL + k0 + ach0]);
            cp16(&As[buf ^ 1][am1][ach1], &g_ctx[(size_t)(m0 + am1) * DMODEL + k0 + ach1]);
            cp16(&Bs[buf ^ 1][bk0][bch0], &Wo[(size_t)(k0 + bk0) * DMODEL + n0 + bch0]);
            cp16(&Bs[buf ^ 1][bk1][bch1], &Wo[(size_t)(k0 + bk1) * DMODEL + n0 + bch1]);
            cp_commit();
            cp_wait<1>();
        } else {
            cp_wait<0>();
        }
        __syncthreads();

#pragma unroll
        for (int ks = 0; ks < 16; ks += 8) {
            unsigned af[2][4], bf[8][2];
#pragma unroll
            for (int i = 0; i < 2; i++) {
                int mr = wm * 32 + i * 16;
                af[i][0] = __float_as_uint(As[buf][mr + g][ks + t]);
                af[i][1] = __float_as_uint(As[buf][mr + g + 8][ks + t]);
                af[i][2] = __float_as_uint(As[buf][mr + g][ks + t + 4]);
                af[i][3] = __float_as_uint(As[buf][mr + g + 8][ks + t + 4]);
            }
#pragma unroll
            for (int j = 0; j < 8; j++) {
                int nr = wn * 64 + j * 8;
                bf[j][0] = __float_as_uint(Bs[buf][ks + t][nr + g]);
                bf[j][1] = __float_as_uint(Bs[buf][ks + t + 4][nr + g]);
            }
#pragma unroll
            for (int i = 0; i < 2; i++)
#pragma unroll
                for (int j = 0; j < 8; j++) mma_tf32(acc[i][j], af[i], bf[j]);
        }
        __syncthreads();
    }

#pragma unroll
    for (int i = 0; i < 2; i++) {
        int r0 = m0 + wm * 32 + i * 16 + g;
#pragma unroll
        for (int j = 0; j < 8; j++) {
            int c = n0 + wn * 64 + j * 8 + 2 * t;
            float2 v0 = make_float2(acc[i][j][0], acc[i][j][1]);
            float2 v1 = make_float2(acc[i][j][2], acc[i][j][3]);
            *(float2*)&g_proj[(size_t)r0 * DMODEL + c] = v0;
            *(float2*)&g_proj[(size_t)(r0 + 8) * DMODEL + c] = v1;
        }
    }
}

// =========================================================================
// Kernel 5: residual + LayerNorm (unchanged).
// =========================================================================
__global__ void ln_kernel(const float* __restrict__ X,
                          const float* __restrict__ gamma,
                          const float* __restrict__ beta,
                          float* __restrict__ out)
{
    const int row = blockIdx.x;
    const int tid = threadIdx.x;
    const float* __restrict__ pr = g_proj + (size_t)row * DMODEL;
    const float* __restrict__ xr = X + (size_t)row * DMODEL;

    float4 p = reinterpret_cast<const float4*>(pr)[tid];
    float4 x = reinterpret_cast<const float4*>(xr)[tid];
    float y0 = p.x + x.x, y1 = p.y + x.y, y2 = p.z + x.z, y3 = p.w + x.w;

    __shared__ float red[8];
    float s = y0 + y1 + y2 + y3;
#pragma unroll
    for (int o = 16; o > 0; o >>= 1) s += __shfl_xor_sync(0xffffffffu, s, o);
    if ((tid & 31) == 0) red[tid >> 5] = s;
    __syncthreads();
    float tot = red[0];
#pragma unroll
    for (int w = 1; w < 8; w++) tot += red[w];
    const float mu = tot * (1.0f / DMODEL);
    __syncthreads();

    float d0 = y0 - mu, d1 = y1 - mu, d2 = y2 - mu, d3 = y3 - mu;
    float sq = d0 * d0 + d1 * d1 + d2 * d2 + d3 * d3;
#pragma unroll
    for (int o = 16; o > 0; o >>= 1) sq += __shfl_xor_sync(0xffffffffu, sq, o);
    if ((tid & 31) == 0) red[tid >> 5] = sq;
    __syncthreads();
    float tot2 = red[0];
#pragma unroll
    for (int w = 1; w < 8; w++) tot2 += red[w];
    const float var = tot2 * (1.0f / DMODEL);
    const float inv = rsqrtf(var + 1e-6f);

    const int c = tid * 4;
    float* __restrict__ orow = out + (size_t)row * DMODEL;
    orow[c + 0] = d0 * inv * gamma[c + 0] + beta[c + 0];
    orow[c + 1] = d1 * inv * gamma[c + 1] + beta[c + 1];
    orow[c + 2] = d2 * inv * gamma[c + 2] + beta[c + 2];
    orow[c + 3] = d3 * inv * gamma[c + 3] + beta[c + 3];
}

// =========================================================================
extern "C" void kernel_launch(void* const* d_in, const int* in_sizes, int n_in,
                              void* d_out, int out_size)
{
    const float* X     = (const float*)d_in[0];
    const int*   mask  = (const int*)d_in[1];
    const float* Wq    = (const float*)d_in[2];
    const float* Wk    = (const float*)d_in[3];
    const float* Wv    = (const float*)d_in[4];
    const float* Wo    = (const float*)d_in[5];
    const float* gamma = (const float*)d_in[6];
    const float* beta  = (const float*)d_in[7];
    float* out = (float*)d_out;

    const long long LN_N   = (long long)BB * LLEN * DMODEL;
    const long long ATTN_N = (long long)BB * NH * LLEN * LLEN;
    float* attn_ptr = ((long long)out_size >= LN_N + ATTN_N) ? (out + LN_N) : nullptr;

    prep_wo_kernel<<<512, 256>>>(Wo);
    qkv_mma_kernel<<<dim3(24, 64), 256>>>(X, Wq, Wk, Wv);
    fused_attn_kernel<<<dim3(64, BB * NH), 256>>>(mask, attn_ptr);
    pv_mma_kernel<<<dim3(8, BB * NH), 256>>>(attn_ptr);
    proj_mma_kernel<<<dim3(8, 64), 256>>>();
    ln_kernel<<<BB * LLEN, 256>>>(X, gamma, beta, out);
}

// round 13
// speedup vs baseline: 1.3615x; 1.0043x over previous
#include <cuda_runtime.h>
#include <cstdint>
#include <math.h>

#define BB 8
#define LLEN 1024
#define DMODEL 1024
#define NH 16
#define DHEAD 64

// ---------------- static scratch (no allocations allowed) ----------------
// g_Q/g_K/g_V/g_ctx hold tf32-rounded bit patterns (stored as float bits).
static __device__ float g_Q[(size_t)BB * NH * LLEN * DHEAD];
static __device__ float g_K[(size_t)BB * NH * LLEN * DHEAD];
static __device__ float g_V[(size_t)BB * NH * LLEN * DHEAD];
static __device__ float g_ctx[(size_t)BB * LLEN * DMODEL];
static __device__ float g_proj[(size_t)BB * LLEN * DMODEL];
static __device__ float g_attn[(size_t)BB * NH * LLEN * LLEN];   // fallback only
static __device__ float g_Woc[(size_t)DMODEL * DMODEL];          // tf32-rounded Wo

// ---------------- tf32 warp-MMA helpers ----------------
__device__ __forceinline__ unsigned f2tf32(float x) {
    unsigned r;
    asm("cvt.rna.tf32.f32 %0, %1;" : "=r"(r) : "f"(x));
    return r;
}
__device__ __forceinline__ float tf32f(float x) {
    return __uint_as_float(f2tf32(x));
}

__device__ __forceinline__ void mma_tf32(float* d, const unsigned* a, const unsigned* b) {
    asm volatile(
        "mma.sync.aligned.m16n8k8.row.col.f32.tf32.tf32.f32 "
        "{%0,%1,%2,%3}, {%4,%5,%6,%7}, {%8,%9}, {%0,%1,%2,%3};\n"
        : "+f"(d[0]), "+f"(d[1]), "+f"(d[2]), "+f"(d[3])
        : "r"(a[0]), "r"(a[1]), "r"(a[2]), "r"(a[3]), "r"(b[0]), "r"(b[1]));
}

__device__ __forceinline__ void cp16(void* smem_dst, const void* gsrc) {
    unsigned s = (unsigned)__cvta_generic_to_shared(smem_dst);
    asm volatile("cp.async.ca.shared.global [%0], [%1], 16;\n" :: "r"(s), "l"(gsrc));
}
__device__ __forceinline__ void cp_commit() {
    asm volatile("cp.async.commit_group;\n");
}
template <int N>
__device__ __forceinline__ void cp_wait() {
    asm volatile("cp.async.wait_group %0;\n" :: "n"(N));
}

// =========================================================================
// Kernel 0: convert only Wo (4MB) to tf32 bits — proj stays CVT-free.
// =========================================================================
__global__ void prep_wo_kernel(const float* __restrict__ Wo)
{
    const size_t N4 = (size_t)DMODEL * DMODEL / 4;
    for (size_t i = (size_t)blockIdx.x * blockDim.x + threadIdx.x;
         i < N4; i += (size_t)gridDim.x * blockDim.x) {
        float4 v = ((const float4*)Wo)[i];
        v.x = tf32f(v.x); v.y = tf32f(v.y); v.z = tf32f(v.z); v.w = tf32f(v.w);
        ((float4*)g_Woc)[i] = v;
    }
}

// =========================================================================
// Kernel 1: fused QKV projection, cp.async 2-stage + 2 CTAs/SM.
// =========================================================================
__global__ __launch_bounds__(256, 2) void qkv_mma_kernel(
    const float* __restrict__ X,
    const float* __restrict__ Wq,
    const float* __restrict__ Wk,
    const float* __restrict__ Wv)
{
    __shared__ float As[2][128][20];
    __shared__ float Bs[2][16][136];

    const int tid  = threadIdx.x;
    const int warp = tid >> 5, lane = tid & 31;
    const int wm = warp >> 1, wn = warp & 1;
    const int g = lane >> 2, t = lane & 3;

    const int m0 = blockIdx.y * 128;
    const int ng = blockIdx.x * 128;
    const int wsel = ng >> 10;
    const int nl = ng & 1023;
    const float* __restrict__ W = (wsel == 0) ? Wq : (wsel == 1 ? Wk : Wv);

    const int am0 = (tid * 2) >> 2,      ach0 = ((tid * 2) & 3) * 4;
    const int am1 = (tid * 2 + 1) >> 2,  ach1 = ((tid * 2 + 1) & 3) * 4;
    const int bk0 = (tid * 2) >> 5,      bch0 = ((tid * 2) & 31) * 4;
    const int bk1 = (tid * 2 + 1) >> 5,  bch1 = ((tid * 2 + 1) & 31) * 4;

    float acc[2][8][4];
#pragma unroll
    for (int i = 0; i < 2; i++)
#pragma unroll
        for (int j = 0; j < 8; j++)
#pragma unroll
            for (int c = 0; c < 4; c++) acc[i][j][c] = 0.f;

    cp16(&As[0][am0][ach0], &X[(size_t)(m0 + am0) * DMODEL + ach0]);
    cp16(&As[0][am1][ach1], &X[(size_t)(m0 + am1) * DMODEL + ach1]);
    cp16(&Bs[0][bk0][bch0], &W[(size_t)bk0 * DMODEL + nl + bch0]);
    cp16(&Bs[0][bk1][bch1], &W[(size_t)bk1 * DMODEL + nl + bch1]);
    cp_commit();

    const int NIT = DMODEL / 16;
    for (int it = 0; it < NIT; it++) {
        const int buf = it & 1;
        if (it + 1 < NIT) {
            const int k0 = (it + 1) * 16;
            cp16(&As[buf ^ 1][am0][ach0], &X[(size_t)(m0 + am0) * DMODEL + k0 + ach0]);
            cp16(&As[buf ^ 1][am1][ach1], &X[(size_t)(m0 + am1) * DMODEL + k0 + ach1]);
            cp16(&Bs[buf ^ 1][bk0][bch0], &W[(size_t)(k0 + bk0) * DMODEL + nl + bch0]);
            cp16(&Bs[buf ^ 1][bk1][bch1], &W[(size_t)(k0 + bk1) * DMODEL + nl + bch1]);
            cp_commit();
            cp_wait<1>();
        } else {
            cp_wait<0>();
        }
        __syncthreads();

#pragma unroll
        for (int ks = 0; ks < 16; ks += 8) {
            unsigned af[2][4], bf[8][2];
#pragma unroll
            for (int i = 0; i < 2; i++) {
                int mr = wm * 32 + i * 16;
                af[i][0] = f2tf32(As[buf][mr + g][ks + t]);
                af[i][1] = f2tf32(As[buf][mr + g + 8][ks + t]);
                af[i][2] = f2tf32(As[buf][mr + g][ks + t + 4]);
                af[i][3] = f2tf32(As[buf][mr + g + 8][ks + t + 4]);
            }
#pragma unroll
            for (int j = 0; j < 8; j++) {
                int nr = wn * 64 + j * 8;
                bf[j][0] = f2tf32(Bs[buf][ks + t][nr + g]);
                bf[j][1] = f2tf32(Bs[buf][ks + t + 4][nr + g]);
            }
#pragma unroll
            for (int i = 0; i < 2; i++)
#pragma unroll
                for (int j = 0; j < 8; j++) mma_tf32(acc[i][j], af[i], bf[j]);
        }
        __syncthreads();
    }

    float* __restrict__ dst = (wsel == 0) ? g_Q : (wsel == 1 ? g_K : g_V);
#pragma unroll
    for (int i = 0; i < 2; i++) {
        int r0 = m0 + wm * 32 + i * 16 + g;
        int b = r0 >> 10, l = r0 & 1023;
#pragma unroll
        for (int j = 0; j < 8; j++) {
            int cl = nl + wn * 64 + j * 8 + 2 * t;
            int h = cl >> 6, d = cl & 63;
            size_t base = ((size_t)(b * NH + h) * LLEN);
            float2 v0 = make_float2(tf32f(acc[i][j][0]), tf32f(acc[i][j][1]));
            float2 v1 = make_float2(tf32f(acc[i][j][2]), tf32f(acc[i][j][3]));
            *(float2*)&dst[(base + l) * DHEAD + d] = v0;
            *(float2*)&dst[(base + l + 8) * DHEAD + d] = v1;
        }
    }
}

// =========================================================================
// Kernel 2: FUSED scores + mask + softmax, cp.async-pipelined K, 2 CTAs/SM.
// =========================================================================
__global__ __launch_bounds__(256, 2) void fused_attn_kernel(
    const int* __restrict__ mask,
    float* __restrict__ attn_ext)
{
    __shared__ float Qs[16][68];        //  4352 B
    __shared__ float Ks[2][64][68];     // 34816 B
    __shared__ float red[16][8];        //   512 B

    const int tid  = threadIdx.x;
    const int warp = tid >> 5, lane = tid & 31;
    const int g = lane >> 2, t = lane & 3;

    const int bh = blockIdx.y;
    const int b  = bh / NH;
    const int m0 = blockIdx.x * 16;
    const float* __restrict__ Q = g_Q + (size_t)bh * LLEN * DHEAD;
    const float* __restrict__ K = g_K + (size_t)bh * LLEN * DHEAD;

    {
        int m = tid >> 4, kq = (tid & 15) * 4;
        *(float4*)&Qs[m][kq] = *(const float4*)&Q[(size_t)(m0 + m) * DHEAD + kq];
    }

#pragma unroll
    for (int r = 0; r < 4; r++) {
        int c = tid + r * 256;
        int row = c >> 4, c4 = (c & 15) * 4;
        cp16(&Ks[0][row][c4], &K[(size_t)row * DHEAD + c4]);
    }
    cp_commit();
    __syncthreads();

    unsigned qf[8][4];
#pragma unroll
    for (int k8 = 0; k8 < 8; k8++) {
        const int ks = k8 * 8;
        qf[k8][0] = __float_as_uint(Qs[g][ks + t]);
        qf[k8][1] = __float_as_uint(Qs[g + 8][ks + t]);
        qf[k8][2] = __float_as_uint(Qs[g][ks + t + 4]);
        qf[k8][3] = __float_as_uint(Qs[g + 8][ks + t + 4]);
    }

    float acc[16][4];
#pragma unroll
    for (int s = 0; s < 16; s++)
#pragma unroll
        for (int c = 0; c < 4; c++) acc[s][c] = 0.f;

#pragma unroll
    for (int it = 0; it < 16; it++) {
        const int buf = it & 1;
        if (it + 1 < 16) {
            const int n0 = (it + 1) * 64;
#pragma unroll
            for (int r = 0; r < 4; r++) {
                int c = tid + r * 256;
                int row = c >> 4, c4 = (c & 15) * 4;
                cp16(&Ks[buf ^ 1][row][c4], &K[(size_t)(n0 + row) * DHEAD + c4]);
            }
            cp_commit();
            cp_wait<1>();
        } else {
            cp_wait<0>();
        }
        __syncthreads();

        const int nr = warp * 8;
#pragma unroll
        for (int k8 = 0; k8 < 8; k8++) {
            const int ks = k8 * 8;
            unsigned bf[2];
            bf[0] = __float_as_uint(Ks[buf][nr + g][ks + t]);
            bf[1] = __float_as_uint(Ks[buf][nr + g][ks + t + 4]);
            mma_tf32(acc[it], qf[k8], bf);
        }
        __syncthreads();
    }

    const float scale = 0.125f;
    const int ql = m0 + g, qh = m0 + g + 8;
    const int* __restrict__ mrl = mask + ((size_t)b * LLEN + ql) * LLEN;
    const int* __restrict__ mrh = mask + ((size_t)b * LLEN + qh) * LLEN;

    float mxl = -3e38f, mxh = -3e38f;
#pragma unroll
    for (int s = 0; s < 16; s++) {
        const int col = s * 64 + warp * 8 + 2 * t;
        const int2 mkl = *(const int2*)&mrl[col];
        const int2 mkh = *(const int2*)&mrh[col];
        float* a = acc[s];
        a[0] = mkl.x ? -1e9f : a[0] * scale;
        a[1] = mkl.y ? -1e9f : a[1] * scale;
        a[2] = mkh.x ? -1e9f : a[2] * scale;
        a[3] = mkh.y ? -1e9f : a[3] * scale;
        mxl = fmaxf(mxl, fmaxf(a[0], a[1]));
        mxh = fmaxf(mxh, fmaxf(a[2], a[3]));
    }
    mxl = fmaxf(mxl, __shfl_xor_sync(0xffffffffu, mxl, 1));
    mxl = fmaxf(mxl, __shfl_xor_sync(0xffffffffu, mxl, 2));
    mxh = fmaxf(mxh, __shfl_xor_sync(0xffffffffu, mxh, 1));
    mxh = fmaxf(mxh, __shfl_xor_sync(0xffffffffu, mxh, 2));
    if (t == 0) { red[g][warp] = mxl; red[g + 8][warp] = mxh; }
    __syncthreads();
    float Ml = red[g][0], Mh = red[g + 8][0];
#pragma unroll
    for (int w = 1; w < 8; w++) {
        Ml = fmaxf(Ml, red[g][w]);
        Mh = fmaxf(Mh, red[g + 8][w]);
    }
    __syncthreads();

    float sl = 0.f, sh = 0.f;
#pragma unroll
    for (int s = 0; s < 16; s++) {
        float* a = acc[s];
        a[0] = __expf(a[0] - Ml);
        a[1] = __expf(a[1] - Ml);
        a[2] = __expf(a[2] - Mh);
        a[3] = __expf(a[3] - Mh);
        sl += a[0] + a[1];
        sh += a[2] + a[3];
    }
    sl += __shfl_xor_sync(0xffffffffu, sl, 1);
    sl += __shfl_xor_sync(0xffffffffu, sl, 2);
    sh += __shfl_xor_sync(0xffffffffu, sh, 1);
    sh += __shfl_xor_sync(0xffffffffu, sh, 2);
    if (t == 0) { red[g][warp] = sl; red[g + 8][warp] = sh; }
    __syncthreads();
    float Sl = 0.f, Sh = 0.f;
#pragma unroll
    for (int w = 0; w < 8; w++) { Sl += red[g][w]; Sh += red[g + 8][w]; }
    const float invl = 1.0f / Sl, invh = 1.0f / Sh;

    float* __restrict__ P = attn_ext ? attn_ext : g_attn;
    float* __restrict__ prl = P + ((size_t)bh * LLEN + ql) * LLEN;
    float* __restrict__ prh = P + ((size_t)bh * LLEN + qh) * LLEN;
#pragma unroll
    for (int s = 0; s < 16; s++) {
        const int col = s * 64 + warp * 8 + 2 * t;
        const float* a = acc[s];
        *(float2*)&prl[col] = make_float2(a[0] * invl, a[1] * invl);
        *(float2*)&prh[col] = make_float2(a[2] * invh, a[3] * invh);
    }
}

// =========================================================================
// Kernel 3: context = P @ V, cp.async 2-stage + 3 CTAs/SM (regs=67 fits).
// =========================================================================
__global__ __launch_bounds__(256, 3) void pv_mma_kernel(const float* __restrict__ attn_ext)
{
    __shared__ float Ps[2][128][20];
    __shared__ float Vs[2][16][72];

    const int tid  = threadIdx.x;
    const int warp = tid >> 5, lane = tid & 31;
    const int wm = warp >> 1, wn = warp & 1;
    const int g = lane >> 2, t = lane & 3;

    const int bh = blockIdx.y;
    const int m0 = blockIdx.x * 128;
    const float* __restrict__ P =
        (attn_ext ? attn_ext : (const float*)g_attn) + (size_t)bh * LLEN * LLEN;
    const float* __restrict__ V = g_V + (size_t)bh * LLEN * DHEAD;

    const int prow = tid >> 2, pc4 = (tid & 3) * 4;
    const int vrow = tid >> 4, vc4 = (tid & 15) * 4;

    float acc[2][4][4];
#pragma unroll
    for (int i = 0; i < 2; i++)
#pragma unroll
        for (int j = 0; j < 4; j++)
#pragma unroll
            for (int c = 0; c < 4; c++) acc[i][j][c] = 0.f;

    {
        cp16(&Ps[0][prow][pc4],      &P[(size_t)(m0 + prow) * LLEN + pc4]);
        cp16(&Ps[0][prow + 64][pc4], &P[(size_t)(m0 + prow + 64) * LLEN + pc4]);
        cp16(&Vs[0][vrow][vc4],      &V[(size_t)vrow * DHEAD + vc4]);
        cp_commit();
    }

    const int NIT = LLEN / 16;
    for (int it = 0; it < NIT; it++) {
        const int buf = it & 1;
        if (it + 1 < NIT) {
            const int k0 = (it + 1) * 16;
            cp16(&Ps[buf ^ 1][prow][pc4],      &P[(size_t)(m0 + prow) * LLEN + k0 + pc4]);
            cp16(&Ps[buf ^ 1][prow + 64][pc4], &P[(size_t)(m0 + prow + 64) * LLEN + k0 + pc4]);
            cp16(&Vs[buf ^ 1][vrow][vc4],      &V[(size_t)(k0 + vrow) * DHEAD + vc4]);
            cp_commit();
            cp_wait<1>();
        } else {
            cp_wait<0>();
        }
        __syncthreads();

#pragma unroll
        for (int ks = 0; ks < 16; ks += 8) {
            unsigned af[2][4], bf[4][2];
#pragma unroll
            for (int i = 0; i < 2; i++) {
                int mr = wm * 32 + i * 16;
                af[i][0] = f2tf32(Ps[buf][mr + g][ks + t]);
                af[i][1] = f2tf32(Ps[buf][mr + g + 8][ks + t]);
                af[i][2] = f2tf32(Ps[buf][mr + g][ks + t + 4]);
                af[i][3] = f2tf32(Ps[buf][mr + g + 8][ks + t + 4]);
            }
#pragma unroll
            for (int j = 0; j < 4; j++) {
                int nr = wn * 32 + j * 8;
                bf[j][0] = __float_as_uint(Vs[buf][ks + t][nr + g]);
                bf[j][1] = __float_as_uint(Vs[buf][ks + t + 4][nr + g]);
            }
#pragma unroll
            for (int i = 0; i < 2; i++)
#pragma unroll
                for (int j = 0; j < 4; j++) mma_tf32(acc[i][j], af[i], bf[j]);
        }
        __syncthreads();
    }

    const int b = bh / NH, h = bh % NH;
#pragma unroll
    for (int i = 0; i < 2; i++) {
        int l0 = m0 + wm * 32 + i * 16 + g;
#pragma unroll
        for (int j = 0; j < 4; j++) {
            int d = wn * 32 + j * 8 + 2 * t;
            float2 v0 = make_float2(tf32f(acc[i][j][0]), tf32f(acc[i][j][1]));
            float2 v1 = make_float2(tf32f(acc[i][j][2]), tf32f(acc[i][j][3]));
            *(float2*)&g_ctx[((size_t)(b * LLEN + l0)) * DMODEL + h * 64 + d] = v0;
            *(float2*)&g_ctx[((size_t)(b * LLEN + l0 + 8)) * DMODEL + h * 64 + d] = v1;
        }
    }
}

// =========================================================================
// Kernel 4: output projection, cp.async 2-stage + 2 CTAs/SM.
// =========================================================================
__global__ __launch_bounds__(256, 2) void proj_mma_kernel()
{
    __shared__ float As[2][128][20];
    __shared__ float Bs[2][16][136];

    const int tid  = threadIdx.x;
    const int warp = tid >> 5, lane = tid & 31;
    const int wm = warp >> 1, wn = warp & 1;
    const int g = lane >> 2, t = lane & 3;

    const int m0 = blockIdx.y * 128;
    const int n0 = blockIdx.x * 128;
    const float* __restrict__ Wo = g_Woc;

    const int am0 = (tid * 2) >> 2,      ach0 = ((tid * 2) & 3) * 4;
    const int am1 = (tid * 2 + 1) >> 2,  ach1 = ((tid * 2 + 1) & 3) * 4;
    const int bk0 = (tid * 2) >> 5,      bch0 = ((tid * 2) & 31) * 4;
    const int bk1 = (tid * 2 + 1) >> 5,  bch1 = ((tid * 2 + 1) & 31) * 4;

    float acc[2][8][4];
#pragma unroll
    for (int i = 0; i < 2; i++)
#pragma unroll
        for (int j = 0; j < 8; j++)
#pragma unroll
            for (int c = 0; c < 4; c++) acc[i][j][c] = 0.f;

    cp16(&As[0][am0][ach0], &g_ctx[(size_t)(m0 + am0) * DMODEL + ach0]);
    cp16(&As[0][am1][ach1], &g_ctx[(size_t)(m0 + am1) * DMODEL + ach1]);
    cp16(&Bs[0][bk0][bch0], &Wo[(size_t)bk0 * DMODEL + n0 + bch0]);
    cp16(&Bs[0][bk1][bch1], &Wo[(size_t)bk1 * DMODEL + n0 + bch1]);
    cp_commit();

    const int NIT = DMODEL / 16;
    for (int it = 0; it < NIT; it++) {
        const int buf = it & 1;
        if (it + 1 < NIT) {
            const int k0 = (it + 1) * 16;
            cp16(&As[buf ^ 1][am0][ach0], &g_ctx[(size_t)(m0 + am0) * DMODEL + k0 + ach0]);
            cp16(&As[buf ^ 1][am1][ach1], &g_ctx[(size_t)(m0 + am1) * DMODEL + k0 + ach1]);
            cp16(&Bs[buf ^ 1][bk0][bch0], &Wo[(size_t)(k0 + bk0) * DMODEL + n0 + bch0]);
            cp16(&Bs[buf ^ 1][bk1][bch1], &Wo[(size_t)(k0 + bk1) * DMODEL + n0 + bch1]);
            cp_commit();
            cp_wait<1>();
        } else {
            cp_wait<0>();
        }
        __syncthreads();

#pragma unroll
        for (int ks = 0; ks < 16; ks += 8) {
            unsigned af[2][4], bf[8][2];
#pragma unroll
            for (int i = 0; i < 2; i++) {
                int mr = wm * 32 + i * 16;
                af[i][0] = __float_as_uint(As[buf][mr + g][ks + t]);
                af[i][1] = __float_as_uint(As[buf][mr + g + 8][ks + t]);
                af[i][2] = __float_as_uint(As[buf][mr + g][ks + t + 4]);
                af[i][3] = __float_as_uint(As[buf][mr + g + 8][ks + t + 4]);
            }
#pragma unroll
            for (int j = 0; j < 8; j++) {
                int nr = wn * 64 + j * 8;
                bf[j][0] = __float_as_uint(Bs[buf][ks + t][nr + g]);
                bf[j][1] = __float_as_uint(Bs[buf][ks + t + 4][nr + g]);
            }
#pragma unroll
            for (int i = 0; i < 2; i++)
#pragma unroll
                for (int j = 0; j < 8; j++) mma_tf32(acc[i][j], af[i], bf[j]);
        }
        __syncthreads();
    }

#pragma unroll
    for (int i = 0; i < 2; i++) {
        int r0 = m0 + wm * 32 + i * 16 + g;
#pragma unroll
        for (int j = 0; j < 8; j++) {
            int c = n0 + wn * 64 + j * 8 + 2 * t;
            float2 v0 = make_float2(acc[i][j][0], acc[i][j][1]);
            float2 v1 = make_float2(acc[i][j][2], acc[i][j][3]);
            *(float2*)&g_proj[(size_t)r0 * DMODEL + c] = v0;
            *(float2*)&g_proj[(size_t)(r0 + 8) * DMODEL + c] = v1;
        }
    }
}

// =========================================================================
// Kernel 5: residual + LayerNorm (unchanged).
// =========================================================================
__global__ void ln_kernel(const float* __restrict__ X,
                          const float* __restrict__ gamma,
                          const float* __restrict__ beta,
                          float* __restrict__ out)
{
    const int row = blockIdx.x;
    const int tid = threadIdx.x;
    const float* __restrict__ pr = g_proj + (size_t)row * DMODEL;
    const float* __restrict__ xr = X + (size_t)row * DMODEL;

    float4 p = reinterpret_cast<const float4*>(pr)[tid];
    float4 x = reinterpret_cast<const float4*>(xr)[tid];
    float y0 = p.x + x.x, y1 = p.y + x.y, y2 = p.z + x.z, y3 = p.w + x.w;

    __shared__ float red[8];
    float s = y0 + y1 + y2 + y3;
#pragma unroll
    for (int o = 16; o > 0; o >>= 1) s += __shfl_xor_sync(0xffffffffu, s, o);
    if ((tid & 31) == 0) red[tid >> 5] = s;
    __syncthreads();
    float tot = red[0];
#pragma unroll
    for (int w = 1; w < 8; w++) tot += red[w];
    const float mu = tot * (1.0f / DMODEL);
    __syncthreads();

    float d0 = y0 - mu, d1 = y1 - mu, d2 = y2 - mu, d3 = y3 - mu;
    float sq = d0 * d0 + d1 * d1 + d2 * d2 + d3 * d3;
#pragma unroll
    for (int o = 16; o > 0; o >>= 1) sq += __shfl_xor_sync(0xffffffffu, sq, o);
    if ((tid & 31) == 0) red[tid >> 5] = sq;
    __syncthreads();
    float tot2 = red[0];
#pragma unroll
    for (int w = 1; w < 8; w++) tot2 += red[w];
    const float var = tot2 * (1.0f / DMODEL);
    const float inv = rsqrtf(var + 1e-6f);

    const int c = tid * 4;
    float* __restrict__ orow = out + (size_t)row * DMODEL;
    orow[c + 0] = d0 * inv * gamma[c + 0] + beta[c + 0];
    orow[c + 1] = d1 * inv * gamma[c + 1] + beta[c + 1];
    orow[c + 2] = d2 * inv * gamma[c + 2] + beta[c + 2];
    orow[c + 3] = d3 * inv * gamma[c + 3] + beta[c + 3];
}

// =========================================================================
extern "C" void kernel_launch(void* const* d_in, const int* in_sizes, int n_in,
                              void* d_out, int out_size)
{
    const float* X     = (const float*)d_in[0];
    const int*   mask  = (const int*)d_in[1];
    const float* Wq    = (const float*)d_in[2];
    const float* Wk    = (const float*)d_in[3];
    const float* Wv    = (const float*)d_in[4];
    const float* Wo    = (const float*)d_in[5];
    const float* gamma = (const float*)d_in[6];
    const float* beta  = (const float*)d_in[7];
    float* out = (float*)d_out;

    const long long LN_N   = (long long)BB * LLEN * DMODEL;
    const long long ATTN_N = (long long)BB * NH * LLEN * LLEN;
    float* attn_ptr = ((long long)out_size >= LN_N + ATTN_N) ? (out + LN_N) : nullptr;

    prep_wo_kernel<<<512, 256>>>(Wo);
    qkv_mma_kernel<<<dim3(24, 64), 256>>>(X, Wq, Wk, Wv);
    fused_attn_kernel<<<dim3(64, BB * NH), 256>>>(mask, attn_ptr);
    pv_mma_kernel<<<dim3(8, BB * NH), 256>>>(attn_ptr);
    proj_mma_kernel<<<dim3(8, 64), 256>>>();
    ln_kernel<<<BB * LLEN, 256>>>(X, gamma, beta, out);
}